// round 15
// baseline (speedup 1.0000x reference)
#include <cuda_runtime.h>
#include <math.h>

#define SS 512
#define CC 384
#define HH 12
#define NPROJ 1152   // 192 qs + 192 ks + 192 vs + 144 qp + 144 kp + 288 vp
#define AD 32        // augmented logit dim (30 used, padded to 32)
#define VD2 48       // padded V row: 16 scalar + 24 point + [40]=1 + pad
#define COMB 576     // 192 scalar_out + 288 pol + 96 norms

// ---------------- scratch (device globals; no allocation allowed) ----------
__device__ float g_proj[SS * NPROJ];
__device__ float g_Qa[HH * AD * SS];     // dim-major augmented Q
__device__ float g_Ka[HH * AD * SS];     // dim-major augmented K
__device__ float g_Vc[HH * SS * VD2];
__device__ float g_attn[HH * SS * SS];   // raw logits (key-masked)
__device__ float g_rowmax[HH * SS];      // per-row logit max
__device__ float g_comb[SS * COMB];
__device__ float g_maskf[SS];

__device__ __forceinline__ void atomicMaxF(float* a, float v) {
    if (v >= 0.0f) atomicMax((int*)a, __float_as_int(v));
    else           atomicMin((unsigned int*)a, (unsigned int)__float_as_int(v));
}

// ---------------- weight/bias column mapping (packed order) ----------------
__device__ __forceinline__ const float* wsrc(int n, int& w,
        const float* Wq_s, const float* Wk_s, const float* Wv_s,
        const float* Wq_p, const float* Wk_p, const float* Wv_p) {
    if (n < 576) {
        w = 192;
        if (n < 192) return Wq_s + n;
        if (n < 384) return Wk_s + (n - 192);
        return Wv_s + (n - 384);
    }
    if (n < 864) {
        w = 144;
        return (n < 720) ? (Wq_p + (n - 576)) : (Wk_p + (n - 720));
    }
    w = 288;
    return Wv_p + (n - 864);
}
__device__ __forceinline__ float bsrc(int n,
        const float* bq_s, const float* bk_s, const float* bv_s,
        const float* bq_p, const float* bk_p, const float* bv_p) {
    if (n < 192)  return bq_s[n];
    if (n < 384)  return bk_s[n - 192];
    if (n < 576)  return bv_s[n - 384];
    if (n < 720)  return bq_p[n - 576];
    if (n < 864)  return bk_p[n - 720];
    return bv_p[n - 864];
}

// ---------------- K1: projection GEMM, reads weight sources directly -------
__global__ void gemm_proj(const float* __restrict__ A, float* __restrict__ Cmat,
        const float* __restrict__ Wq_s, const float* __restrict__ Wk_s,
        const float* __restrict__ Wv_s, const float* __restrict__ Wq_p,
        const float* __restrict__ Wk_p, const float* __restrict__ Wv_p,
        const float* __restrict__ bq_s, const float* __restrict__ bk_s,
        const float* __restrict__ bv_s, const float* __restrict__ bq_p,
        const float* __restrict__ bk_p, const float* __restrict__ bv_p) {
    const int K = CC, N = NPROJ;
    __shared__ __align__(16) float As[2][16][64];
    __shared__ __align__(16) float Ws[2][16][64];
    int tid = threadIdx.x;
    int tx = tid & 15, ty = tid >> 4;
    int n0 = blockIdx.x * 64, m0 = blockIdx.y * 64;

    int kkA[4], mA[4], nW[4], kkW[4];
    const float* bW[4];  int wstr[4];
    #pragma unroll
    for (int l = 0; l < 4; ++l) {
        int e = tid + l * 256;
        kkA[l] = e & 15;  mA[l] = e >> 4;
        nW[l]  = e & 63;  kkW[l] = e >> 6;
        bW[l] = wsrc(n0 + nW[l], wstr[l], Wq_s, Wk_s, Wv_s, Wq_p, Wk_p, Wv_p);
    }
    #pragma unroll
    for (int l = 0; l < 4; ++l) {
        As[0][kkA[l]][mA[l]] = A[(m0 + mA[l]) * K + kkA[l]];
        Ws[0][kkW[l]][nW[l]] = bW[l][kkW[l] * wstr[l]];
    }
    __syncthreads();

    float acc[4][4] = {};
    int nt = K >> 4;
    for (int t = 0; t < nt; ++t) {
        int cur = t & 1;
        float ar[4], wr[4];
        if (t + 1 < nt) {
            int k0n = (t + 1) << 4;
            #pragma unroll
            for (int l = 0; l < 4; ++l) {
                ar[l] = A[(m0 + mA[l]) * K + k0n + kkA[l]];
                wr[l] = bW[l][(k0n + kkW[l]) * wstr[l]];
            }
        }
        #pragma unroll
        for (int kk = 0; kk < 16; ++kk) {
            float4 a4 = *(const float4*)&As[cur][kk][ty * 4];
            float4 b4 = *(const float4*)&Ws[cur][kk][tx * 4];
            float av[4] = {a4.x, a4.y, a4.z, a4.w};
            float bv[4] = {b4.x, b4.y, b4.z, b4.w};
            #pragma unroll
            for (int i = 0; i < 4; ++i)
                #pragma unroll
                for (int j = 0; j < 4; ++j) acc[i][j] += av[i] * bv[j];
        }
        if (t + 1 < nt) {
            #pragma unroll
            for (int l = 0; l < 4; ++l) {
                As[cur ^ 1][kkA[l]][mA[l]] = ar[l];
                Ws[cur ^ 1][kkW[l]][nW[l]] = wr[l];
            }
        }
        __syncthreads();
    }
    float bj[4];
    #pragma unroll
    for (int j = 0; j < 4; ++j)
        bj[j] = bsrc(n0 + tx * 4 + j, bq_s, bk_s, bv_s, bq_p, bk_p, bv_p);
    #pragma unroll
    for (int i = 0; i < 4; ++i) {
        int m = m0 + ty * 4 + i;
        #pragma unroll
        for (int j = 0; j < 4; ++j)
            Cmat[m * N + n0 + tx * 4 + j] = acc[i][j] + bj[j];
    }
}

// ---------------- generic SGEMM (double-buffered, 256 thr, 4x4 microtile) --
__global__ void gemm64(const float* __restrict__ A, const float* __restrict__ W,
                       const float* __restrict__ bias, float* __restrict__ Cmat,
                       int M, int N, int K, const float* __restrict__ mask) {
    __shared__ __align__(16) float As[2][16][64];
    __shared__ __align__(16) float Ws[2][16][64];
    int tid = threadIdx.x;
    int tx = tid & 15, ty = tid >> 4;
    int n0 = blockIdx.x * 64, m0 = blockIdx.y * 64;

    int kkA[4], mA[4], nW[4], kkW[4];
    #pragma unroll
    for (int l = 0; l < 4; ++l) {
        int e = tid + l * 256;
        kkA[l] = e & 15;  mA[l] = e >> 4;
        nW[l]  = e & 63;  kkW[l] = e >> 6;
    }
    #pragma unroll
    for (int l = 0; l < 4; ++l) {
        As[0][kkA[l]][mA[l]] = A[(m0 + mA[l]) * K + kkA[l]];
        Ws[0][kkW[l]][nW[l]] = W[kkW[l] * N + n0 + nW[l]];
    }
    __syncthreads();

    float acc[4][4] = {};
    int nt = K >> 4;
    for (int t = 0; t < nt; ++t) {
        int cur = t & 1;
        float ar[4], wr[4];
        if (t + 1 < nt) {
            int k0n = (t + 1) << 4;
            #pragma unroll
            for (int l = 0; l < 4; ++l) {
                ar[l] = A[(m0 + mA[l]) * K + k0n + kkA[l]];
                wr[l] = W[(k0n + kkW[l]) * N + n0 + nW[l]];
            }
        }
        #pragma unroll
        for (int kk = 0; kk < 16; ++kk) {
            float4 a4 = *(const float4*)&As[cur][kk][ty * 4];
            float4 b4 = *(const float4*)&Ws[cur][kk][tx * 4];
            float av[4] = {a4.x, a4.y, a4.z, a4.w};
            float bv[4] = {b4.x, b4.y, b4.z, b4.w};
            #pragma unroll
            for (int i = 0; i < 4; ++i)
                #pragma unroll
                for (int j = 0; j < 4; ++j) acc[i][j] += av[i] * bv[j];
        }
        if (t + 1 < nt) {
            #pragma unroll
            for (int l = 0; l < 4; ++l) {
                As[cur ^ 1][kkA[l]][mA[l]] = ar[l];
                Ws[cur ^ 1][kkW[l]][nW[l]] = wr[l];
            }
        }
        __syncthreads();
    }
    #pragma unroll
    for (int i = 0; i < 4; ++i) {
        int m = m0 + ty * 4 + i;
        float sc = mask ? mask[m] : 1.0f;
        #pragma unroll
        for (int j = 0; j < 4; ++j) {
            int n = n0 + tx * 4 + j;
            Cmat[m * N + n] = (acc[i][j] + bias[n]) * sc;
        }
    }
}

// ---------------- K2: rotate + pack; block 0 canonicalizes mask ------------
__global__ void rotate_pack(const float* __restrict__ rot, const float* __restrict__ trans,
                            const float* __restrict__ pw,
                            const unsigned char* __restrict__ msk) {
    int s = blockIdx.x;
    int t = threadIdx.x;                 // 128 threads
    __shared__ float pts[576];
    __shared__ float Rs[9], ts_[3], spw_s[48];
    __shared__ int flag;

    if (blockIdx.x == 0) {               // mask canonicalize + rowmax init
        if (t == 0) flag = 0;
        __syncthreads();
        for (int b = t; b < 512; b += 128)
            if ((b & 3) != 0 && msk[b] != 0) atomicOr(&flag, 1);
        __syncthreads();
        for (int i = t; i < SS; i += 128)
            g_maskf[i] = flag ? (msk[i] != 0 ? 1.0f : 0.0f)
                              : (((const int*)msk)[i] != 0 ? 1.0f : 0.0f);
        for (int i = t; i < HH * SS; i += 128)
            g_rowmax[i] = -__int_as_float(0x7F800000);   // -inf
    }
    if (t < 9) Rs[t] = rot[s * 9 + t];
    if (t >= 16 && t < 19) ts_[t - 16] = trans[s * 3 + (t - 16)];
    if (t >= 64 && t < 112) {            // softplus(point_weights)
        float x = pw[t - 64];
        spw_s[t - 64] = (x > 20.0f) ? x : log1pf(expf(x));
    }
    const float* pr = g_proj + s * NPROJ;

    // V pad columns: [40]=1 (softmax denominator), [41..47]=0
    for (int e = t; e < HH * 8; e += 128) {
        int h = e >> 3, c = 40 + (e & 7);
        g_Vc[(h * SS + s) * VD2 + c] = (c == 40) ? 1.0f : 0.0f;
    }
    #pragma unroll
    for (int e = t; e < 576; e += 128) {
        float v = pr[e];
        int seg = e / 192, r = e % 192;
        int h = r >> 4, d = r & 15;
        if      (seg == 0) g_Qa[h * (AD * SS) + d * SS + s] = 0.25f * v;
        else if (seg == 1) g_Ka[h * (AD * SS) + d * SS + s] = v;
        else               g_Vc[(h * SS + s) * VD2 + d] = v;
    }
    #pragma unroll
    for (int e = t; e < 576; e += 128) pts[e] = pr[576 + e];
    __syncthreads();

    if (t < 24) {
        bool isQ = t < 12;
        int h = isQ ? t : t - 12;
        const float* p = pts + (isQ ? 0 : 144) + h * 12;
        float* base = (isQ ? g_Qa : g_Ka) + h * (AD * SS);
        float s2 = 0.0f;
        #pragma unroll
        for (int pp = 0; pp < 4; ++pp) {
            float x = p[pp * 3 + 0], y = p[pp * 3 + 1], z = p[pp * 3 + 2];
            float gx = Rs[0] * x + Rs[1] * y + Rs[2] * z + ts_[0];
            float gy = Rs[3] * x + Rs[4] * y + Rs[5] * z + ts_[1];
            float gz = Rs[6] * x + Rs[7] * y + Rs[8] * z + ts_[2];
            float w = spw_s[h * 4 + pp];
            s2 += w * (gx * gx + gy * gy + gz * gz);
            float m = isQ ? w : 1.0f;
            base[(16 + pp * 3 + 0) * SS + s] = m * gx;
            base[(16 + pp * 3 + 1) * SS + s] = m * gy;
            base[(16 + pp * 3 + 2) * SS + s] = m * gz;
        }
        base[28 * SS + s] = isQ ? -0.5f * s2 : 1.0f;
        base[29 * SS + s] = isQ ? 1.0f : -0.5f * s2;
        base[30 * SS + s] = 0.0f;
        base[31 * SS + s] = 0.0f;
    } else if (t >= 32 && t < 128) {
        int q = t - 32;                   // 96 v-point tasks
        const float* p = pts + 288 + q * 3;
        float* o = g_Vc + ((q >> 3) * SS + s) * VD2 + 16 + (q & 7) * 3;
        float x = p[0], y = p[1], z = p[2];
        o[0] = Rs[0] * x + Rs[1] * y + Rs[2] * z + ts_[0];
        o[1] = Rs[3] * x + Rs[4] * y + Rs[5] * z + ts_[1];
        o[2] = Rs[6] * x + Rs[7] * y + Rs[8] * z + ts_[2];
    }
}

// ---------------- K3: raw logits + per-row max (atomics) -------------------
__global__ void logits_gemm() {
    int h = blockIdx.z;
    int n0 = blockIdx.x * 128, m0 = blockIdx.y * 64;
    __shared__ __align__(16) float Qs[AD][64];
    __shared__ __align__(16) float Ks[AD][128];
    int tid = threadIdx.x;               // 256
    const float* qb = g_Qa + h * (AD * SS);
    const float* kb = g_Ka + h * (AD * SS);
    #pragma unroll
    for (int l = 0; l < 2; ++l) {
        int idx = tid + l * 256;
        int k = idx >> 4, m4 = idx & 15;
        *(float4*)&Qs[k][m4 * 4] = *(const float4*)&qb[k * SS + m0 + m4 * 4];
    }
    #pragma unroll
    for (int l = 0; l < 4; ++l) {
        int idx = tid + l * 256;
        int k = idx >> 5, n4 = idx & 31;
        *(float4*)&Ks[k][n4 * 4] = *(const float4*)&kb[k * SS + n0 + n4 * 4];
    }
    __syncthreads();
    int tx = tid & 31, ty = tid >> 5;    // warp = ty (32 lanes = tx)
    float acc[8][4] = {};
    #pragma unroll
    for (int k = 0; k < AD; ++k) {
        float4 b4 = *(const float4*)&Ks[k][tx * 4];
        float4 a0 = *(const float4*)&Qs[k][ty * 8];
        float4 a1 = *(const float4*)&Qs[k][ty * 8 + 4];
        float av[8] = {a0.x, a0.y, a0.z, a0.w, a1.x, a1.y, a1.z, a1.w};
        float bv[4] = {b4.x, b4.y, b4.z, b4.w};
        #pragma unroll
        for (int i = 0; i < 8; ++i)
            #pragma unroll
            for (int j = 0; j < 4; ++j) acc[i][j] += av[i] * bv[j];
    }
    float4 mq = ((const float4*)g_maskf)[(n0 >> 2) + tx];
    float rmax[8];
    #pragma unroll
    for (int i = 0; i < 8; ++i) {
        int m = m0 + ty * 8 + i;
        float4 v;
        v.x = (mq.x != 0.0f) ? acc[i][0] : -10000.0f;
        v.y = (mq.y != 0.0f) ? acc[i][1] : -10000.0f;
        v.z = (mq.z != 0.0f) ? acc[i][2] : -10000.0f;
        v.w = (mq.w != 0.0f) ? acc[i][3] : -10000.0f;
        *(float4*)&g_attn[(h * SS + m) * SS + n0 + tx * 4] = v;
        rmax[i] = fmaxf(fmaxf(v.x, v.y), fmaxf(v.z, v.w));
    }
    // warp-reduce row maxima (warp ty owns rows ty*8..+7 completely)
    #pragma unroll
    for (int o = 16; o; o >>= 1)
        #pragma unroll
        for (int i = 0; i < 8; ++i)
            rmax[i] = fmaxf(rmax[i], __shfl_xor_sync(0xFFFFFFFFu, rmax[i], o));
    if (tx == 0) {
        #pragma unroll
        for (int i = 0; i < 8; ++i)
            atomicMaxF(&g_rowmax[h * SS + m0 + ty * 8 + i], rmax[i]);
    }
}

// ---------------- K4: exp(P-m)@Vpad (denominator = col 40), epilogue norm --
// Block = (h, 16 queries), 192 threads = 16q x 12 float4-groups. Grid 384.
__global__ void __launch_bounds__(192) attn_apply(
        const float* __restrict__ rot, const float* __restrict__ trans) {
    int h = blockIdx.y, i0 = blockIdx.x * 16;
    __shared__ __align__(16) float at[16][68];   // exp(logits) tile (padded)
    __shared__ __align__(16) float vv[64][VD2];
    __shared__ __align__(16) float ot[16][VD2];
    __shared__ float mxs[16];
    int tid = threadIdx.x;                       // 192
    int il = tid / 12, dg = tid - il * 12;
    if (tid < 16) mxs[tid] = g_rowmax[h * SS + i0 + tid];
    __syncthreads();
    float4 acc = make_float4(0.f, 0.f, 0.f, 0.f);

    for (int j0 = 0; j0 < SS; j0 += 64) {
        #pragma unroll
        for (int l = 0; l < 2; ++l) {            // 256 float4 fills of at
            int idx = tid + l * 192;
            if (idx < 256) {
                int rr = idx >> 4, c4 = idx & 15;
                float m = mxs[rr];
                float4 g = *(const float4*)&g_attn[(h * SS + i0 + rr) * SS + j0 + c4 * 4];
                float4 e;
                e.x = __expf(g.x - m);  e.y = __expf(g.y - m);
                e.z = __expf(g.z - m);  e.w = __expf(g.w - m);
                *(float4*)&at[rr][c4 * 4] = e;
            }
        }
        #pragma unroll
        for (int l = 0; l < 4; ++l) {            // 768 float4 fills of vv
            int idx = tid + l * 192;
            int rr = idx / 12, c4 = idx % 12;
            *(float4*)&vv[rr][c4 * 4] =
                *(const float4*)&g_Vc[(h * SS + j0 + rr) * VD2 + c4 * 4];
        }
        __syncthreads();
        #pragma unroll 8
        for (int jj = 0; jj < 64; ++jj) {
            float a = at[il][jj];
            float4 v4 = *(const float4*)&vv[jj][dg * 4];
            acc.x += a * v4.x;  acc.y += a * v4.y;
            acc.z += a * v4.z;  acc.w += a * v4.w;
        }
        __syncthreads();
    }
    *(float4*)&ot[il][dg * 4] = acc;
    __syncthreads();

    // epilogue: normalize by ot[q][40] (>= 1 by max-subtraction), query mask
    {   // scalar copies: 16q x 16d = 256 tasks
        #pragma unroll
        for (int l = 0; l < 2; ++l) {
            int e = tid + l * 192;
            if (e < 256) {
                int q = e >> 4, d = e & 15;
                float inv = g_maskf[i0 + q] / ot[q][40];
                g_comb[(i0 + q) * COMB + h * 16 + d] = ot[q][d] * inv;
            }
        }
    }
    if (tid < 128) {                              // 16q x 8p point tasks
        int q = tid >> 3, p = tid & 7;
        int s = i0 + q;
        float inv = g_maskf[s] / ot[q][40];
        float v0 = ot[q][16 + 3 * p + 0] * inv - trans[s * 3 + 0];
        float v1 = ot[q][16 + 3 * p + 1] * inv - trans[s * 3 + 1];
        float v2 = ot[q][16 + 3 * p + 2] * inv - trans[s * 3 + 2];
        const float* R = rot + s * 9;
        float p0 = R[0] * v0 + R[3] * v1 + R[6] * v2;   // R^T v
        float p1 = R[1] * v0 + R[4] * v1 + R[7] * v2;
        float p2 = R[2] * v0 + R[5] * v1 + R[8] * v2;
        float* cb = g_comb + s * COMB;
        cb[192 + (h * 8 + p) * 3 + 0] = p0;
        cb[192 + (h * 8 + p) * 3 + 1] = p1;
        cb[192 + (h * 8 + p) * 3 + 2] = p2;
        cb[480 + h * 8 + p] = sqrtf(p0 * p0 + p1 * p1 + p2 * p2);
    }
}

// ---------------------------------------------------------------------------
extern "C" void kernel_launch(void* const* d_in, const int* in_sizes, int n_in,
                              void* d_out, int out_size) {
    const float* single = (const float*)d_in[0];
    const float* rot    = (const float*)d_in[1];
    const float* trans  = (const float*)d_in[2];
    const float* Wq_s = (const float*)d_in[3];  const float* bq_s = (const float*)d_in[4];
    const float* Wk_s = (const float*)d_in[5];  const float* bk_s = (const float*)d_in[6];
    const float* Wv_s = (const float*)d_in[7];  const float* bv_s = (const float*)d_in[8];
    const float* Wq_p = (const float*)d_in[9];  const float* bq_p = (const float*)d_in[10];
    const float* Wk_p = (const float*)d_in[11]; const float* bk_p = (const float*)d_in[12];
    const float* Wv_p = (const float*)d_in[13]; const float* bv_p = (const float*)d_in[14];
    const float* pw   = (const float*)d_in[15];
    const float* Wo   = (const float*)d_in[16];
    const float* bo   = (const float*)d_in[17];
    const unsigned char* mask = (const unsigned char*)d_in[18];
    float* out = (float*)d_out;

    float *pproj, *pcomb, *pmaskf;
    cudaGetSymbolAddress((void**)&pproj,  g_proj);
    cudaGetSymbolAddress((void**)&pcomb,  g_comb);
    cudaGetSymbolAddress((void**)&pmaskf, g_maskf);

    gemm_proj<<<dim3(NPROJ / 64, SS / 64), 256>>>(single, pproj,
        Wq_s, Wk_s, Wv_s, Wq_p, Wk_p, Wv_p,
        bq_s, bk_s, bv_s, bq_p, bk_p, bv_p);
    rotate_pack<<<SS, 128>>>(rot, trans, pw, mask);
    logits_gemm<<<dim3(SS / 128, SS / 64, HH), 256>>>();
    attn_apply<<<dim3(SS / 16, HH), 192>>>(rot, trans);
    gemm64<<<dim3(CC / 64, SS / 64), 256>>>(pcomb, Wo, bo, out, SS, CC, COMB, pmaskf);
}